// round 1
// baseline (speedup 1.0000x reference)
#include <cuda_runtime.h>
#include <cuda_bf16.h>

// Problem constants
#define BATCH 2
#define SEQ   2048
#define DIM   1024
#define HEADS 16
#define HD    64
#define MROWS (BATCH*SEQ)      // 4096
#define NQKV  (3*DIM)          // 3072

// Scratch (device globals: allocation-free)
__device__ float g_q[BATCH*HEADS*SEQ*HD];     // [b,h,s,d]
__device__ float g_k[BATCH*HEADS*SEQ*HD];
__device__ float g_v[BATCH*HEADS*SEQ*HD];
__device__ float g_attn[BATCH*SEQ*DIM];       // [b,s,h*64+d]

// ---------------------------------------------------------------------------
// SGEMM: C[m,n] = sum_k A[m,k] * W[n,k] + bias[n]
// 128x128 tile, BK=16, 256 threads, 8x8 per-thread register tile.
// SCATTER=1: scatter into g_q/g_k/g_v   SCATTER=0: plain row-major to out
// ---------------------------------------------------------------------------
template<int SCATTER>
__global__ __launch_bounds__(256)
void gemm_bias_kernel(const float* __restrict__ A,
                      const float* __restrict__ W,
                      const float* __restrict__ bias,
                      float* __restrict__ out)
{
    const int K = 1024;
    __shared__ float As[16][128];
    __shared__ float Bs[16][128];

    const int tid = threadIdx.x;
    const int m0 = blockIdx.y * 128;
    const int n0 = blockIdx.x * 128;
    const int tx = tid & 15;       // 0..15 -> col group
    const int ty = tid >> 4;       // 0..15 -> row group

    float acc[8][8];
#pragma unroll
    for (int i = 0; i < 8; ++i)
#pragma unroll
        for (int j = 0; j < 8; ++j) acc[i][j] = 0.f;

    for (int k0 = 0; k0 < K; k0 += 16) {
        // load 128x16 tiles of A and W, transposed into [k][row]
#pragma unroll
        for (int t = tid; t < 512; t += 256) {
            const int row = t >> 2;
            const int kc  = (t & 3) << 2;
            float4 a = *(const float4*)&A[(long)(m0 + row) * K + k0 + kc];
            As[kc+0][row] = a.x; As[kc+1][row] = a.y;
            As[kc+2][row] = a.z; As[kc+3][row] = a.w;
            float4 b = *(const float4*)&W[(long)(n0 + row) * K + k0 + kc];
            Bs[kc+0][row] = b.x; Bs[kc+1][row] = b.y;
            Bs[kc+2][row] = b.z; Bs[kc+3][row] = b.w;
        }
        __syncthreads();

#pragma unroll
        for (int kk = 0; kk < 16; ++kk) {
            float4 a0 = *(const float4*)&As[kk][ty*8];
            float4 a1 = *(const float4*)&As[kk][ty*8 + 4];
            float4 b0 = *(const float4*)&Bs[kk][tx*8];
            float4 b1 = *(const float4*)&Bs[kk][tx*8 + 4];
            float av[8] = {a0.x,a0.y,a0.z,a0.w,a1.x,a1.y,a1.z,a1.w};
            float bv[8] = {b0.x,b0.y,b0.z,b0.w,b1.x,b1.y,b1.z,b1.w};
#pragma unroll
            for (int i = 0; i < 8; ++i)
#pragma unroll
                for (int j = 0; j < 8; ++j)
                    acc[i][j] = fmaf(av[i], bv[j], acc[i][j]);
        }
        __syncthreads();
    }

    // epilogue
#pragma unroll
    for (int i = 0; i < 8; ++i) {
        const int m = m0 + ty*8 + i;
#pragma unroll
        for (int j = 0; j < 8; ++j) {
            const int n = n0 + tx*8 + j;
            const float v = acc[i][j] + bias[n];
            if (SCATTER) {
                const int b = m >> 11, s = m & 2047;
                const int part = n >> 10, h = (n >> 6) & 15, d = n & 63;
                float* dst = (part == 0) ? g_q : (part == 1) ? g_k : g_v;
                dst[((((long)b*HEADS + h)*SEQ) + s)*HD + d] = v;
            } else {
                out[(long)m * 1024 + n] = v;
            }
        }
    }
}

// ---------------------------------------------------------------------------
// Flash attention, fp32. BQ=64, BKV=64, 256 threads (16x16), 4x4 reg tiles.
// Q/K stored d-major in smem (conflict-free LDS.128), V c-major, S [64][65].
// ---------------------------------------------------------------------------
#define FLASH_SMEM ((64*64*3 + 64*65 + 3*64) * 4)

__global__ __launch_bounds__(256)
void flash_kernel(float* __restrict__ Ob)
{
    extern __shared__ float sm[];
    float* Qs  = sm;                 // [d][r] : Qs[d*64 + r]
    float* Ks  = Qs + 64*64;         // [d][c]
    float* Vs  = Ks + 64*64;         // [c][d]
    float* Ss  = Vs + 64*64;         // [r][c] pitch 65
    float* mrow = Ss + 64*65;
    float* lrow = mrow + 64;
    float* arow = lrow + 64;

    const int tid = threadIdx.x;
    const int tx = tid & 15;
    const int ty = tid >> 4;
    const int bh = blockIdx.y;                 // 0..31
    const int q0 = blockIdx.x * 64;

    const float* Qg = g_q + ((long)bh*SEQ + q0) * HD;
    const float* Kg = g_k + (long)bh*SEQ*HD;
    const float* Vg = g_v + (long)bh*SEQ*HD;

    // load Q tile (transposed to d-major)
#pragma unroll
    for (int t = tid; t < 1024; t += 256) {
        const int r = t >> 4;
        const int dc = (t & 15) << 2;
        float4 q4 = *(const float4*)&Qg[r*HD + dc];
        Qs[(dc+0)*64 + r] = q4.x; Qs[(dc+1)*64 + r] = q4.y;
        Qs[(dc+2)*64 + r] = q4.z; Qs[(dc+3)*64 + r] = q4.w;
    }
    if (tid < 64) { mrow[tid] = -1e30f; lrow[tid] = 0.f; }

    float o[4][4];
#pragma unroll
    for (int i = 0; i < 4; ++i)
#pragma unroll
        for (int j = 0; j < 4; ++j) o[i][j] = 0.f;

    const float scale = 0.125f;   // 1/sqrt(64)

    for (int kt = 0; kt < SEQ/64; ++kt) {
        __syncthreads();   // prior PV done / Q+init visible
        const float* Kt = Kg + (long)kt*64*HD;
        const float* Vt = Vg + (long)kt*64*HD;
#pragma unroll
        for (int t = tid; t < 1024; t += 256) {
            const int r = t >> 4;
            const int dc = (t & 15) << 2;
            float4 k4 = *(const float4*)&Kt[r*HD + dc];
            Ks[(dc+0)*64 + r] = k4.x; Ks[(dc+1)*64 + r] = k4.y;
            Ks[(dc+2)*64 + r] = k4.z; Ks[(dc+3)*64 + r] = k4.w;
            float4 v4 = *(const float4*)&Vt[r*HD + dc];
            *(float4*)&Vs[r*64 + dc] = v4;
        }
        __syncthreads();

        // S = scale * Q K^T  (4x4 per thread)
        float acc[4][4];
#pragma unroll
        for (int i = 0; i < 4; ++i)
#pragma unroll
            for (int j = 0; j < 4; ++j) acc[i][j] = 0.f;
#pragma unroll
        for (int d = 0; d < 64; ++d) {
            float4 a = *(const float4*)&Qs[d*64 + ty*4];
            float4 b = *(const float4*)&Ks[d*64 + tx*4];
            float av[4] = {a.x,a.y,a.z,a.w};
            float bv[4] = {b.x,b.y,b.z,b.w};
#pragma unroll
            for (int i = 0; i < 4; ++i)
#pragma unroll
                for (int j = 0; j < 4; ++j)
                    acc[i][j] = fmaf(av[i], bv[j], acc[i][j]);
        }
#pragma unroll
        for (int i = 0; i < 4; ++i)
#pragma unroll
            for (int j = 0; j < 4; ++j)
                Ss[(ty*4+i)*65 + tx*4+j] = acc[i][j] * scale;
        __syncthreads();

        // online softmax: 4 threads per row
        {
            const int row = tid >> 2;
            const int g = tid & 3;
            const float mold = mrow[row];
            float tmax = -1e30f;
#pragma unroll
            for (int j = 0; j < 16; ++j)
                tmax = fmaxf(tmax, Ss[row*65 + g*16 + j]);
            tmax = fmaxf(tmax, __shfl_xor_sync(0xffffffffu, tmax, 1));
            tmax = fmaxf(tmax, __shfl_xor_sync(0xffffffffu, tmax, 2));
            const float mnew = fmaxf(mold, tmax);
            const float alpha = __expf(mold - mnew);
            float s = 0.f;
#pragma unroll
            for (int j = 0; j < 16; ++j) {
                const float p = __expf(Ss[row*65 + g*16 + j] - mnew);
                Ss[row*65 + g*16 + j] = p;
                s += p;
            }
            s += __shfl_xor_sync(0xffffffffu, s, 1);
            s += __shfl_xor_sync(0xffffffffu, s, 2);
            if (g == 0) {
                mrow[row] = mnew;
                lrow[row] = lrow[row] * alpha + s;
                arow[row] = alpha;
            }
        }
        __syncthreads();

        // O = O*alpha + P @ V
        float ar[4];
#pragma unroll
        for (int i = 0; i < 4; ++i) ar[i] = arow[ty*4 + i];
#pragma unroll
        for (int i = 0; i < 4; ++i)
#pragma unroll
            for (int j = 0; j < 4; ++j) o[i][j] *= ar[i];
#pragma unroll
        for (int c = 0; c < 64; ++c) {
            float pv[4];
#pragma unroll
            for (int i = 0; i < 4; ++i) pv[i] = Ss[(ty*4+i)*65 + c];
            float4 b = *(const float4*)&Vs[c*64 + tx*4];
            float bv[4] = {b.x,b.y,b.z,b.w};
#pragma unroll
            for (int i = 0; i < 4; ++i)
#pragma unroll
                for (int j = 0; j < 4; ++j)
                    o[i][j] = fmaf(pv[i], bv[j], o[i][j]);
        }
    }

    // finalize + store to [B,S,D] layout
    const int b = bh >> 4, h = bh & 15;
#pragma unroll
    for (int i = 0; i < 4; ++i) {
        const int r = ty*4 + i;
        const float inv = 1.f / lrow[r];
        float4 v4 = make_float4(o[i][0]*inv, o[i][1]*inv, o[i][2]*inv, o[i][3]*inv);
        *(float4*)&Ob[(((long)b*SEQ + q0 + r)*DIM) + h*HD + tx*4] = v4;
    }
}

// ---------------------------------------------------------------------------
extern "C" void kernel_launch(void* const* d_in, const int* in_sizes, int n_in,
                              void* d_out, int out_size)
{
    const float* x      = (const float*)d_in[0];
    const float* w_qkv  = (const float*)d_in[1];
    const float* b_qkv  = (const float*)d_in[2];
    const float* w_proj = (const float*)d_in[3];
    const float* b_proj = (const float*)d_in[4];
    float* out = (float*)d_out;

    float* attn_ptr = nullptr;
    cudaGetSymbolAddress((void**)&attn_ptr, g_attn);

    // 1) QKV GEMM + bias, scatter into Q/K/V [b,h,s,d]
    {
        dim3 grid(NQKV/128, MROWS/128);   // (24, 32)
        gemm_bias_kernel<1><<<grid, 256>>>(x, w_qkv, b_qkv, nullptr);
    }
    // 2) flash attention -> g_attn [b,s,D]
    {
        cudaFuncSetAttribute(flash_kernel,
                             cudaFuncAttributeMaxDynamicSharedMemorySize,
                             FLASH_SMEM);
        dim3 grid(SEQ/64, BATCH*HEADS);   // (32, 32)
        flash_kernel<<<grid, 256, FLASH_SMEM>>>(attn_ptr);
    }
    // 3) output projection + bias
    {
        dim3 grid(DIM/128, MROWS/128);    // (8, 32)
        gemm_bias_kernel<0><<<grid, 256>>>(attn_ptr, w_proj, b_proj, out);
    }
}

// round 3
// speedup vs baseline: 3.1109x; 3.1109x over previous
#include <cuda_runtime.h>
#include <cuda_bf16.h>
#include <cstdint>

// Problem constants
#define BATCH 2
#define SEQ   2048
#define DIM   1024
#define HEADS 16
#define HD    64
#define MROWS (BATCH*SEQ)      // 4096
#define NQKV  (3*DIM)          // 3072

// Scratch (device globals: allocation-free)
__device__ float g_q[BATCH*HEADS*SEQ*HD];     // [b,h,s,d]
__device__ float g_k[BATCH*HEADS*SEQ*HD];
__device__ float g_v[BATCH*HEADS*SEQ*HD];
__device__ float g_attn[BATCH*SEQ*DIM];       // [b,s,h*64+d]

// ---------------------------------------------------------------------------
// helpers
// ---------------------------------------------------------------------------
__device__ __forceinline__ uint32_t f2tf32(float f) {
    uint32_t u;
    asm("cvt.rna.tf32.f32 %0, %1;" : "=r"(u) : "f"(f));
    return u;
}
__device__ __forceinline__ float ftf32(float f) { return __uint_as_float(f2tf32(f)); }

__device__ __forceinline__ void mma_tf32(float c[4], const uint32_t a[4], const uint32_t b[2]) {
    asm volatile(
        "mma.sync.aligned.m16n8k8.row.col.f32.tf32.tf32.f32 "
        "{%0,%1,%2,%3},{%4,%5,%6,%7},{%8,%9},{%0,%1,%2,%3};\n"
        : "+f"(c[0]), "+f"(c[1]), "+f"(c[2]), "+f"(c[3])
        : "r"(a[0]), "r"(a[1]), "r"(a[2]), "r"(a[3]), "r"(b[0]), "r"(b[1]));
}

// ---------------------------------------------------------------------------
// TF32 GEMM: C[m,n] = sum_k A[m,k]*W[n,k] + bias[n]
// BM=BN=128, BK=32, 256 threads, cp.async 2-stage, warp tile 32x64.
// SCATTER=1: scatter into g_q/g_k/g_v.  SCATTER=0: row-major out (N=1024).
// ---------------------------------------------------------------------------
#define PK 36
#define GEMM_SMEM (2*2*128*PK*4)

template<int SCATTER>
__global__ __launch_bounds__(256)
void gemm_tf32(const float* __restrict__ A,
               const float* __restrict__ W,
               const float* __restrict__ bias,
               float* __restrict__ out)
{
    extern __shared__ float sm[];
    float* As = sm;               // [2][128][PK]
    float* Bs = sm + 2*128*PK;    // [2][128][PK]

    const int tid  = threadIdx.x;
    const int wid  = tid >> 5;
    const int lane = tid & 31;
    const int m0 = blockIdx.y * 128;
    const int n0 = blockIdx.x * 128;
    const int wm = (wid & 3) * 32;
    const int wn = (wid >> 2) * 64;
    const int tg = lane >> 2;     // 0..7
    const int tk = lane & 3;      // 0..3

    float acc[2][8][4];
#pragma unroll
    for (int mt = 0; mt < 2; ++mt)
#pragma unroll
        for (int nt = 0; nt < 8; ++nt)
#pragma unroll
            for (int c = 0; c < 4; ++c) acc[mt][nt][c] = 0.f;

    const int K = 1024;
    const int NS = K / 32;

    // stage s into buffer buf
    auto stage = [&](int s, int buf) {
        const int k0 = s * 32;
#pragma unroll
        for (int i = 0; i < 4; ++i) {
            const int t   = tid + i * 256;   // 0..1023
            const int row = t >> 3;          // 0..127
            const int kc  = (t & 7) << 2;    // 0..28
            uint32_t sa = (uint32_t)__cvta_generic_to_shared(
                &As[buf*128*PK + row*PK + kc]);
            const float* ga = &A[(long)(m0 + row) * K + k0 + kc];
            asm volatile("cp.async.cg.shared.global [%0], [%1], 16;\n"
                         :: "r"(sa), "l"(ga));
            uint32_t sb = (uint32_t)__cvta_generic_to_shared(
                &Bs[buf*128*PK + row*PK + kc]);
            const float* gb = &W[(long)(n0 + row) * K + k0 + kc];
            asm volatile("cp.async.cg.shared.global [%0], [%1], 16;\n"
                         :: "r"(sb), "l"(gb));
        }
        asm volatile("cp.async.commit_group;\n");
    };

    stage(0, 0);

    for (int s = 0; s < NS; ++s) {
        const int buf = s & 1;
        if (s + 1 < NS) {
            stage(s + 1, buf ^ 1);
            asm volatile("cp.async.wait_group 1;\n");
        } else {
            asm volatile("cp.async.wait_group 0;\n");
        }
        __syncthreads();

        const float* as = &As[buf*128*PK];
        const float* bs = &Bs[buf*128*PK];
#pragma unroll
        for (int k8 = 0; k8 < 32; k8 += 8) {
            uint32_t af[2][4], bf[8][2];
#pragma unroll
            for (int mt = 0; mt < 2; ++mt) {
                const float* p = &as[(wm + mt*16 + tg)*PK + k8 + tk];
                af[mt][0] = f2tf32(p[0]);
                af[mt][1] = f2tf32(p[8*PK]);
                af[mt][2] = f2tf32(p[4]);
                af[mt][3] = f2tf32(p[8*PK + 4]);
            }
#pragma unroll
            for (int nt = 0; nt < 8; ++nt) {
                const float* p = &bs[(wn + nt*8 + tg)*PK + k8 + tk];
                bf[nt][0] = f2tf32(p[0]);
                bf[nt][1] = f2tf32(p[4]);
            }
#pragma unroll
            for (int mt = 0; mt < 2; ++mt)
#pragma unroll
                for (int nt = 0; nt < 8; ++nt)
                    mma_tf32(acc[mt][nt], af[mt], bf[nt]);
        }
        __syncthreads();
    }

    // epilogue
#pragma unroll
    for (int mt = 0; mt < 2; ++mt) {
#pragma unroll
        for (int nt = 0; nt < 8; ++nt) {
#pragma unroll
            for (int c = 0; c < 4; ++c) {
                const int m = m0 + wm + mt*16 + tg + ((c >= 2) ? 8 : 0);
                const int n = n0 + wn + nt*8 + 2*tk + (c & 1);
                const float v = acc[mt][nt][c] + bias[n];
                if (SCATTER) {
                    const int b = m >> 11, sq = m & 2047;
                    const int part = n >> 10, h = (n >> 6) & 15, d = n & 63;
                    float* dst = (part == 0) ? g_q : (part == 1) ? g_k : g_v;
                    dst[((((long)b*HEADS + h)*SEQ) + sq)*HD + d] = v;
                } else {
                    out[(long)m * 1024 + n] = v;
                }
            }
        }
    }
}

// ---------------------------------------------------------------------------
// Flash attention (TF32 mma). BQ=64, BKV=64, 256 threads = 8 warps.
// Warp tile 16x32 (warp_m=wid>>1, warp_n=wid&1). Smem tiles tf32-rounded.
// ---------------------------------------------------------------------------
#define QP 68
#define VP 72
#define FLASH_SMEM ((64*QP*3 + 64*VP + 3*64) * 4)

__global__ __launch_bounds__(256)
void flash_tf32(float* __restrict__ Ob)
{
    extern __shared__ float sm[];
    float* Qs = sm;                 // [r][d] pitch QP
    float* Ks = Qs + 64*QP;         // [kv][d] pitch QP
    float* Vs = Ks + 64*QP;         // [kv][d] pitch VP
    float* Ss = Vs + 64*VP;         // [r][kv] pitch QP
    float* mrow = Ss + 64*QP;
    float* lrow = mrow + 64;
    float* arow = lrow + 64;

    const int tid  = threadIdx.x;
    const int wid  = tid >> 5;
    const int lane = tid & 31;
    const int tg = lane >> 2;   // 0..7
    const int tk = lane & 3;    // 0..3
    const int wm = (wid >> 1) * 16;
    const int wn = (wid & 1) * 32;

    const int bh = blockIdx.y;
    const int q0 = blockIdx.x * 64;

    const float* Qg = g_q + ((long)bh*SEQ + q0) * HD;
    const float* Kg = g_k + (long)bh*SEQ*HD;
    const float* Vg = g_v + (long)bh*SEQ*HD;

    // load Q tile, tf32-rounded
#pragma unroll
    for (int t = tid; t < 1024; t += 256) {
        const int r = t >> 4;
        const int c = (t & 15) << 2;
        float4 q4 = *(const float4*)&Qg[r*HD + c];
        float4 o4 = make_float4(ftf32(q4.x), ftf32(q4.y), ftf32(q4.z), ftf32(q4.w));
        *(float4*)&Qs[r*QP + c] = o4;
    }
    if (tid < 64) { mrow[tid] = -1e30f; lrow[tid] = 0.f; }

    float oacc[4][4];
#pragma unroll
    for (int nt = 0; nt < 4; ++nt)
#pragma unroll
        for (int c = 0; c < 4; ++c) oacc[nt][c] = 0.f;

    const float scale = 0.125f;  // 1/sqrt(64)

    for (int kt = 0; kt < SEQ/64; ++kt) {
        __syncthreads();  // prior PV done; Q/init visible on first iter
        const float* Kt = Kg + (long)kt*64*HD;
        const float* Vt = Vg + (long)kt*64*HD;
#pragma unroll
        for (int t = tid; t < 1024; t += 256) {
            const int r = t >> 4;
            const int c = (t & 15) << 2;
            float4 k4 = *(const float4*)&Kt[r*HD + c];
            *(float4*)&Ks[r*QP + c] =
                make_float4(ftf32(k4.x), ftf32(k4.y), ftf32(k4.z), ftf32(k4.w));
            float4 v4 = *(const float4*)&Vt[r*HD + c];
            *(float4*)&Vs[r*VP + c] =
                make_float4(ftf32(v4.x), ftf32(v4.y), ftf32(v4.z), ftf32(v4.w));
        }
        __syncthreads();

        // S = scale * Q K^T : warp tile 16x32
        {
            float sacc[4][4];
#pragma unroll
            for (int nt = 0; nt < 4; ++nt)
#pragma unroll
                for (int c = 0; c < 4; ++c) sacc[nt][c] = 0.f;
#pragma unroll
            for (int k8 = 0; k8 < 64; k8 += 8) {
                uint32_t af[4], bf[4][2];
                const float* pa = &Qs[(wm + tg)*QP + k8 + tk];
                af[0] = __float_as_uint(pa[0]);
                af[1] = __float_as_uint(pa[8*QP]);
                af[2] = __float_as_uint(pa[4]);
                af[3] = __float_as_uint(pa[8*QP + 4]);
#pragma unroll
                for (int nt = 0; nt < 4; ++nt) {
                    const float* pb = &Ks[(wn + nt*8 + tg)*QP + k8 + tk];
                    bf[nt][0] = __float_as_uint(pb[0]);
                    bf[nt][1] = __float_as_uint(pb[4]);
                }
#pragma unroll
                for (int nt = 0; nt < 4; ++nt)
                    mma_tf32(sacc[nt], af, bf[nt]);
            }
#pragma unroll
            for (int nt = 0; nt < 4; ++nt) {
                const int col = wn + nt*8 + 2*tk;
                Ss[(wm + tg)*QP + col]     = sacc[nt][0] * scale;
                Ss[(wm + tg)*QP + col + 1] = sacc[nt][1] * scale;
                Ss[(wm + tg + 8)*QP + col]     = sacc[nt][2] * scale;
                Ss[(wm + tg + 8)*QP + col + 1] = sacc[nt][3] * scale;
            }
        }
        __syncthreads();

        // online softmax: 4 threads per row
        {
            const int row = tid >> 2;
            const int g = tid & 3;
            const float mold = mrow[row];
            float tmax = -1e30f;
#pragma unroll
            for (int j = 0; j < 16; ++j)
                tmax = fmaxf(tmax, Ss[row*QP + g*16 + j]);
            tmax = fmaxf(tmax, __shfl_xor_sync(0xffffffffu, tmax, 1));
            tmax = fmaxf(tmax, __shfl_xor_sync(0xffffffffu, tmax, 2));
            const float mnew = fmaxf(mold, tmax);
            const float alpha = __expf(mold - mnew);
            float ssum = 0.f;
#pragma unroll
            for (int j = 0; j < 16; ++j) {
                const float p = ftf32(__expf(Ss[row*QP + g*16 + j] - mnew));
                Ss[row*QP + g*16 + j] = p;
                ssum += p;
            }
            ssum += __shfl_xor_sync(0xffffffffu, ssum, 1);
            ssum += __shfl_xor_sync(0xffffffffu, ssum, 2);
            if (g == 0) {
                mrow[row] = mnew;
                lrow[row] = lrow[row] * alpha + ssum;
                arow[row] = alpha;
            }
        }
        __syncthreads();

        // O = O*alpha + P @ V : warp tile 16x32 over hd
        {
            const float a0 = arow[wm + tg];
            const float a1 = arow[wm + tg + 8];
#pragma unroll
            for (int nt = 0; nt < 4; ++nt) {
                oacc[nt][0] *= a0; oacc[nt][1] *= a0;
                oacc[nt][2] *= a1; oacc[nt][3] *= a1;
            }
#pragma unroll
            for (int k8 = 0; k8 < 64; k8 += 8) {
                uint32_t af[4], bf[4][2];
                const float* pa = &Ss[(wm + tg)*QP + k8 + tk];
                af[0] = __float_as_uint(pa[0]);
                af[1] = __float_as_uint(pa[8*QP]);
                af[2] = __float_as_uint(pa[4]);
                af[3] = __float_as_uint(pa[8*QP + 4]);
#pragma unroll
                for (int nt = 0; nt < 4; ++nt) {
                    const float* pb = &Vs[(k8 + tk)*VP + wn + nt*8 + tg];
                    bf[nt][0] = __float_as_uint(pb[0]);
                    bf[nt][1] = __float_as_uint(pb[4*VP]);
                }
#pragma unroll
                for (int nt = 0; nt < 4; ++nt)
                    mma_tf32(oacc[nt], af, bf[nt]);
            }
        }
    }
    __syncthreads();

    // finalize + store to [B,S,D]
    const int b = bh >> 4, h = bh & 15;
    const float inv0 = 1.f / lrow[wm + tg];
    const float inv1 = 1.f / lrow[wm + tg + 8];
#pragma unroll
    for (int nt = 0; nt < 4; ++nt) {
        const int col = h*HD + wn + nt*8 + 2*tk;
        const int r0 = q0 + wm + tg;
        const int r1 = r0 + 8;
        *(float2*)&Ob[((long)b*SEQ + r0)*DIM + col] =
            make_float2(oacc[nt][0]*inv0, oacc[nt][1]*inv0);
        *(float2*)&Ob[((long)b*SEQ + r1)*DIM + col] =
            make_float2(oacc[nt][2]*inv1, oacc[nt][3]*inv1);
    }
}

// ---------------------------------------------------------------------------
extern "C" void kernel_launch(void* const* d_in, const int* in_sizes, int n_in,
                              void* d_out, int out_size)
{
    const float* x      = (const float*)d_in[0];
    const float* w_qkv  = (const float*)d_in[1];
    const float* b_qkv  = (const float*)d_in[2];
    const float* w_proj = (const float*)d_in[3];
    const float* b_proj = (const float*)d_in[4];
    float* out = (float*)d_out;

    float* attn_ptr = nullptr;
    cudaGetSymbolAddress((void**)&attn_ptr, g_attn);

    static bool attr_done = false;
    if (!attr_done) {
        cudaFuncSetAttribute(gemm_tf32<1>,
            cudaFuncAttributeMaxDynamicSharedMemorySize, GEMM_SMEM);
        cudaFuncSetAttribute(gemm_tf32<0>,
            cudaFuncAttributeMaxDynamicSharedMemorySize, GEMM_SMEM);
        cudaFuncSetAttribute(flash_tf32,
            cudaFuncAttributeMaxDynamicSharedMemorySize, FLASH_SMEM);
        attr_done = true;
    }

    // 1) QKV GEMM + bias -> scatter into Q/K/V [b,h,s,d]
    {
        dim3 grid(NQKV/128, MROWS/128);   // (24, 32)
        gemm_tf32<1><<<grid, 256, GEMM_SMEM>>>(x, w_qkv, b_qkv, nullptr);
    }
    // 2) flash attention -> g_attn [b,s,D]
    {
        dim3 grid(SEQ/64, BATCH*HEADS);   // (32, 32)
        flash_tf32<<<grid, 256, FLASH_SMEM>>>(attn_ptr);
    }
    // 3) output projection + bias
    {
        dim3 grid(DIM/128, MROWS/128);    // (8, 32)
        gemm_tf32<0><<<grid, 256, GEMM_SMEM>>>(attn_ptr, w_proj, b_proj, out);
    }
}

// round 6
// speedup vs baseline: 3.1553x; 1.0143x over previous
#include <cuda_runtime.h>
#include <cuda_bf16.h>
#include <cstdint>

// Problem constants
#define BATCH 2
#define SEQ   2048
#define DIM   1024
#define HEADS 16
#define HD    64
#define MROWS (BATCH*SEQ)      // 4096
#define NQKV  (3*DIM)          // 3072

// Scratch (device globals: allocation-free)
__device__ float g_q[BATCH*HEADS*SEQ*HD];     // [b,h,s,d]
__device__ float g_k[BATCH*HEADS*SEQ*HD];
__device__ float g_v[BATCH*HEADS*SEQ*HD];
__device__ float g_attn[BATCH*SEQ*DIM];       // [b,s,h*64+d] (tf32-rounded)
__device__ float g_xr[MROWS*DIM];             // x rounded to tf32
__device__ float g_wqkvr[NQKV*DIM];           // w_qkv rounded to tf32
__device__ float g_wprojr[DIM*DIM];           // w_proj rounded to tf32

// ---------------------------------------------------------------------------
// helpers
// ---------------------------------------------------------------------------
__device__ __forceinline__ uint32_t f2tf32(float f) {
    uint32_t u;
    asm("cvt.rna.tf32.f32 %0, %1;" : "=r"(u) : "f"(f));
    return u;
}
__device__ __forceinline__ float ftf32(float f) { return __uint_as_float(f2tf32(f)); }

__device__ __forceinline__ void mma_tf32(float c[4], const uint32_t a[4], const uint32_t b[2]) {
    asm volatile(
        "mma.sync.aligned.m16n8k8.row.col.f32.tf32.tf32.f32 "
        "{%0,%1,%2,%3},{%4,%5,%6,%7},{%8,%9},{%0,%1,%2,%3};\n"
        : "+f"(c[0]), "+f"(c[1]), "+f"(c[2]), "+f"(c[3])
        : "r"(a[0]), "r"(a[1]), "r"(a[2]), "r"(a[3]), "r"(b[0]), "r"(b[1]));
}

// ---------------------------------------------------------------------------
// Elementwise tf32 rounding pre-pass (RNA). n must be divisible by 4.
// ---------------------------------------------------------------------------
__global__ __launch_bounds__(256)
void round_tf32_kernel(const float* __restrict__ in, float* __restrict__ out, int n4)
{
    int i = blockIdx.x * 256 + threadIdx.x;
    if (i < n4) {
        float4 v = ((const float4*)in)[i];
        ((float4*)out)[i] = make_float4(ftf32(v.x), ftf32(v.y), ftf32(v.z), ftf32(v.w));
    }
}

// ---------------------------------------------------------------------------
// TF32 GEMM: C[m,n] = sum_k A[m,k]*W[n,k] + bias[n]
// A, W must already be tf32-rounded. No cvt in the mainloop.
// BM=BN=128, BK=32, 256 threads, cp.async 2-stage, warp tile 32x64.
// ---------------------------------------------------------------------------
#define PK 36
#define GEMM_SMEM (2*2*128*PK*4)

template<int SCATTER>
__global__ __launch_bounds__(256)
void gemm_tf32(const float* __restrict__ A,
               const float* __restrict__ W,
               const float* __restrict__ bias,
               float* __restrict__ out)
{
    extern __shared__ float sm[];
    float* As = sm;               // [2][128][PK]
    float* Bs = sm + 2*128*PK;    // [2][128][PK]

    const int tid  = threadIdx.x;
    const int wid  = tid >> 5;
    const int lane = tid & 31;
    const int m0 = blockIdx.y * 128;
    const int n0 = blockIdx.x * 128;
    const int wm = (wid & 3) * 32;
    const int wn = (wid >> 2) * 64;
    const int tg = lane >> 2;     // 0..7
    const int tk = lane & 3;      // 0..3

    float acc[2][8][4];
#pragma unroll
    for (int mt = 0; mt < 2; ++mt)
#pragma unroll
        for (int nt = 0; nt < 8; ++nt)
#pragma unroll
            for (int c = 0; c < 4; ++c) acc[mt][nt][c] = 0.f;

    const int K = 1024;
    const int NS = K / 32;

    auto stage = [&](int s, int buf) {
        const int k0 = s * 32;
#pragma unroll
        for (int i = 0; i < 4; ++i) {
            const int t   = tid + i * 256;   // 0..1023
            const int row = t >> 3;          // 0..127
            const int kc  = (t & 7) << 2;    // 0..28
            uint32_t sa = (uint32_t)__cvta_generic_to_shared(
                &As[buf*128*PK + row*PK + kc]);
            const float* ga = &A[(long)(m0 + row) * K + k0 + kc];
            asm volatile("cp.async.cg.shared.global [%0], [%1], 16;\n"
                         :: "r"(sa), "l"(ga));
            uint32_t sb = (uint32_t)__cvta_generic_to_shared(
                &Bs[buf*128*PK + row*PK + kc]);
            const float* gb = &W[(long)(n0 + row) * K + k0 + kc];
            asm volatile("cp.async.cg.shared.global [%0], [%1], 16;\n"
                         :: "r"(sb), "l"(gb));
        }
        asm volatile("cp.async.commit_group;\n");
    };

    stage(0, 0);

    for (int s = 0; s < NS; ++s) {
        const int buf = s & 1;
        if (s + 1 < NS) {
            stage(s + 1, buf ^ 1);
            asm volatile("cp.async.wait_group 1;\n");
        } else {
            asm volatile("cp.async.wait_group 0;\n");
        }
        __syncthreads();

        const float* as = &As[buf*128*PK];
        const float* bs = &Bs[buf*128*PK];
#pragma unroll
        for (int k8 = 0; k8 < 32; k8 += 8) {
            uint32_t af[2][4], bf[8][2];
#pragma unroll
            for (int mt = 0; mt < 2; ++mt) {
                const float* p = &as[(wm + mt*16 + tg)*PK + k8 + tk];
                af[mt][0] = __float_as_uint(p[0]);
                af[mt][1] = __float_as_uint(p[8*PK]);
                af[mt][2] = __float_as_uint(p[4]);
                af[mt][3] = __float_as_uint(p[8*PK + 4]);
            }
#pragma unroll
            for (int nt = 0; nt < 8; ++nt) {
                const float* p = &bs[(wn + nt*8 + tg)*PK + k8 + tk];
                bf[nt][0] = __float_as_uint(p[0]);
                bf[nt][1] = __float_as_uint(p[4]);
            }
#pragma unroll
            for (int mt = 0; mt < 2; ++mt)
#pragma unroll
                for (int nt = 0; nt < 8; ++nt)
                    mma_tf32(acc[mt][nt], af[mt], bf[nt]);
        }
        __syncthreads();
    }

    // epilogue
#pragma unroll
    for (int mt = 0; mt < 2; ++mt) {
#pragma unroll
        for (int nt = 0; nt < 8; ++nt) {
#pragma unroll
            for (int c = 0; c < 4; ++c) {
                const int m = m0 + wm + mt*16 + tg + ((c >= 2) ? 8 : 0);
                const int n = n0 + wn + nt*8 + 2*tk + (c & 1);
                const float v = acc[mt][nt][c] + bias[n];
                if (SCATTER) {
                    const int b = m >> 11, sq = m & 2047;
                    const int part = n >> 10, h = (n >> 6) & 15, d = n & 63;
                    float* dst = (part == 0) ? g_q : (part == 1) ? g_k : g_v;
                    dst[((((long)b*HEADS + h)*SEQ) + sq)*HD + d] = ftf32(v);
                } else {
                    out[(long)m * 1024 + n] = v;
                }
            }
        }
    }
}

// ---------------------------------------------------------------------------
// Flash attention (TF32 mma). BQ=64, BKV=64, 256 threads = 8 warps.
// Q/K/V arrive already tf32-rounded (QKV epilogue) -> no cvt at STS.
// Output rounded to tf32 in epilogue (feeds proj GEMM raw-bit path).
// ---------------------------------------------------------------------------
#define QP 68
#define VP 72
#define FLASH_SMEM ((64*QP*3 + 64*VP + 3*64) * 4)

__global__ __launch_bounds__(256)
void flash_tf32(float* __restrict__ Ob)
{
    extern __shared__ float sm[];
    float* Qs = sm;                 // [r][d] pitch QP
    float* Ks = Qs + 64*QP;         // [kv][d] pitch QP
    float* Vs = Ks + 64*QP;         // [kv][d] pitch VP
    float* Ss = Vs + 64*VP;         // [r][kv] pitch QP
    float* mrow = Ss + 64*QP;
    float* lrow = mrow + 64;
    float* arow = lrow + 64;

    const int tid  = threadIdx.x;
    const int wid  = tid >> 5;
    const int lane = tid & 31;
    const int tg = lane >> 2;   // 0..7
    const int tk = lane & 3;    // 0..3
    const int wm = (wid >> 1) * 16;
    const int wn = (wid & 1) * 32;

    const int bh = blockIdx.y;
    const int q0 = blockIdx.x * 64;

    const float* Qg = g_q + ((long)bh*SEQ + q0) * HD;
    const float* Kg = g_k + (long)bh*SEQ*HD;
    const float* Vg = g_v + (long)bh*SEQ*HD;

    // load Q tile (already tf32-rounded)
#pragma unroll
    for (int t = tid; t < 1024; t += 256) {
        const int r = t >> 4;
        const int c = (t & 15) << 2;
        *(float4*)&Qs[r*QP + c] = *(const float4*)&Qg[r*HD + c];
    }
    if (tid < 64) { mrow[tid] = -1e30f; lrow[tid] = 0.f; }

    float oacc[4][4];
#pragma unroll
    for (int nt = 0; nt < 4; ++nt)
#pragma unroll
        for (int c = 0; c < 4; ++c) oacc[nt][c] = 0.f;

    const float scale = 0.125f;  // 1/sqrt(64)

    for (int kt = 0; kt < SEQ/64; ++kt) {
        __syncthreads();  // prior PV done; Q/init visible on first iter
        const float* Kt = Kg + (long)kt*64*HD;
        const float* Vt = Vg + (long)kt*64*HD;
#pragma unroll
        for (int t = tid; t < 1024; t += 256) {
            const int r = t >> 4;
            const int c = (t & 15) << 2;
            *(float4*)&Ks[r*QP + c] = *(const float4*)&Kt[r*HD + c];
            *(float4*)&Vs[r*VP + c] = *(const float4*)&Vt[r*HD + c];
        }
        __syncthreads();

        // S = scale * Q K^T : warp tile 16x32
        {
            float sacc[4][4];
#pragma unroll
            for (int nt = 0; nt < 4; ++nt)
#pragma unroll
                for (int c = 0; c < 4; ++c) sacc[nt][c] = 0.f;
#pragma unroll
            for (int k8 = 0; k8 < 64; k8 += 8) {
                uint32_t af[4], bf[4][2];
                const float* pa = &Qs[(wm + tg)*QP + k8 + tk];
                af[0] = __float_as_uint(pa[0]);
                af[1] = __float_as_uint(pa[8*QP]);
                af[2] = __float_as_uint(pa[4]);
                af[3] = __float_as_uint(pa[8*QP + 4]);
#pragma unroll
                for (int nt = 0; nt < 4; ++nt) {
                    const float* pb = &Ks[(wn + nt*8 + tg)*QP + k8 + tk];
                    bf[nt][0] = __float_as_uint(pb[0]);
                    bf[nt][1] = __float_as_uint(pb[4]);
                }
#pragma unroll
                for (int nt = 0; nt < 4; ++nt)
                    mma_tf32(sacc[nt], af, bf[nt]);
            }
#pragma unroll
            for (int nt = 0; nt < 4; ++nt) {
                const int col = wn + nt*8 + 2*tk;
                Ss[(wm + tg)*QP + col]     = sacc[nt][0] * scale;
                Ss[(wm + tg)*QP + col + 1] = sacc[nt][1] * scale;
                Ss[(wm + tg + 8)*QP + col]     = sacc[nt][2] * scale;
                Ss[(wm + tg + 8)*QP + col + 1] = sacc[nt][3] * scale;
            }
        }
        __syncthreads();

        // online softmax: 4 threads per row
        {
            const int row = tid >> 2;
            const int g = tid & 3;
            const float mold = mrow[row];
            float tmax = -1e30f;
#pragma unroll
            for (int j = 0; j < 16; ++j)
                tmax = fmaxf(tmax, Ss[row*QP + g*16 + j]);
            tmax = fmaxf(tmax, __shfl_xor_sync(0xffffffffu, tmax, 1));
            tmax = fmaxf(tmax, __shfl_xor_sync(0xffffffffu, tmax, 2));
            const float mnew = fmaxf(mold, tmax);
            const float alpha = __expf(mold - mnew);
            float ssum = 0.f;
#pragma unroll
            for (int j = 0; j < 16; ++j) {
                const float p = ftf32(__expf(Ss[row*QP + g*16 + j] - mnew));
                Ss[row*QP + g*16 + j] = p;
                ssum += p;
            }
            ssum += __shfl_xor_sync(0xffffffffu, ssum, 1);
            ssum += __shfl_xor_sync(0xffffffffu, ssum, 2);
            if (g == 0) {
                mrow[row] = mnew;
                lrow[row] = lrow[row] * alpha + ssum;
                arow[row] = alpha;
            }
        }
        __syncthreads();

        // O = O*alpha + P @ V : warp tile 16x32 over hd
        {
            const float a0 = arow[wm + tg];
            const float a1 = arow[wm + tg + 8];
#pragma unroll
            for (int nt = 0; nt < 4; ++nt) {
                oacc[nt][0] *= a0; oacc[nt][1] *= a0;
                oacc[nt][2] *= a1; oacc[nt][3] *= a1;
            }
#pragma unroll
            for (int k8 = 0; k8 < 64; k8 += 8) {
                uint32_t af[4], bf[4][2];
                const float* pa = &Ss[(wm + tg)*QP + k8 + tk];
                af[0] = __float_as_uint(pa[0]);
                af[1] = __float_as_uint(pa[8*QP]);
                af[2] = __float_as_uint(pa[4]);
                af[3] = __float_as_uint(pa[8*QP + 4]);
#pragma unroll
                for (int nt = 0; nt < 4; ++nt) {
                    const float* pb = &Vs[(k8 + tk)*VP + wn + nt*8 + tg];
                    bf[nt][0] = __float_as_uint(pb[0]);
                    bf[nt][1] = __float_as_uint(pb[4*VP]);
                }
#pragma unroll
                for (int nt = 0; nt < 4; ++nt)
                    mma_tf32(oacc[nt], af, bf[nt]);
            }
        }
    }
    __syncthreads();

    // finalize + store (tf32-rounded) to [B,S,D]
    const int b = bh >> 4, h = bh & 15;
    const float inv0 = 1.f / lrow[wm + tg];
    const float inv1 = 1.f / lrow[wm + tg + 8];
#pragma unroll
    for (int nt = 0; nt < 4; ++nt) {
        const int col = h*HD + wn + nt*8 + 2*tk;
        const int r0 = q0 + wm + tg;
        const int r1 = r0 + 8;
        *(float2*)&Ob[((long)b*SEQ + r0)*DIM + col] =
            make_float2(ftf32(oacc[nt][0]*inv0), ftf32(oacc[nt][1]*inv0));
        *(float2*)&Ob[((long)b*SEQ + r1)*DIM + col] =
            make_float2(ftf32(oacc[nt][2]*inv1), ftf32(oacc[nt][3]*inv1));
    }
}

// ---------------------------------------------------------------------------
extern "C" void kernel_launch(void* const* d_in, const int* in_sizes, int n_in,
                              void* d_out, int out_size)
{
    const float* x      = (const float*)d_in[0];
    const float* w_qkv  = (const float*)d_in[1];
    const float* b_qkv  = (const float*)d_in[2];
    const float* w_proj = (const float*)d_in[3];
    const float* b_proj = (const float*)d_in[4];
    float* out = (float*)d_out;

    float *attn_ptr = nullptr, *xr = nullptr, *wqkvr = nullptr, *wprojr = nullptr;
    cudaGetSymbolAddress((void**)&attn_ptr, g_attn);
    cudaGetSymbolAddress((void**)&xr, g_xr);
    cudaGetSymbolAddress((void**)&wqkvr, g_wqkvr);
    cudaGetSymbolAddress((void**)&wprojr, g_wprojr);

    static bool attr_done = false;
    if (!attr_done) {
        cudaFuncSetAttribute(gemm_tf32<1>,
            cudaFuncAttributeMaxDynamicSharedMemorySize, GEMM_SMEM);
        cudaFuncSetAttribute(gemm_tf32<0>,
            cudaFuncAttributeMaxDynamicSharedMemorySize, GEMM_SMEM);
        cudaFuncSetAttribute(flash_tf32,
            cudaFuncAttributeMaxDynamicSharedMemorySize, FLASH_SMEM);
        attr_done = true;
    }

    // 0) tf32 rounding pre-pass (RNA) for GEMM operands
    {
        int n4x = MROWS*DIM/4, n4q = NQKV*DIM/4, n4p = DIM*DIM/4;
        round_tf32_kernel<<<(n4x+255)/256, 256>>>(x, xr, n4x);
        round_tf32_kernel<<<(n4q+255)/256, 256>>>(w_qkv, wqkvr, n4q);
        round_tf32_kernel<<<(n4p+255)/256, 256>>>(w_proj, wprojr, n4p);
    }
    // 1) QKV GEMM + bias -> scatter into Q/K/V [b,h,s,d] (tf32-rounded)
    {
        dim3 grid(NQKV/128, MROWS/128);   // (24, 32)
        gemm_tf32<1><<<grid, 256, GEMM_SMEM>>>(xr, wqkvr, b_qkv, nullptr);
    }
    // 2) flash attention -> g_attn [b,s,D] (tf32-rounded)
    {
        dim3 grid(SEQ/64, BATCH*HEADS);   // (32, 32)
        flash_tf32<<<grid, 256, FLASH_SMEM>>>(attn_ptr);
    }
    // 3) output projection + bias -> d_out
    {
        dim3 grid(DIM/128, MROWS/128);    // (8, 32)
        gemm_tf32<0><<<grid, 256, GEMM_SMEM>>>(attn_ptr, wprojr, b_proj, out);
    }
}

// round 7
// speedup vs baseline: 3.8245x; 1.2121x over previous
#include <cuda_runtime.h>
#include <cuda_bf16.h>
#include <cstdint>

// Problem constants
#define BATCH 2
#define SEQ   2048
#define DIM   1024
#define HEADS 16
#define HD    64
#define MROWS (BATCH*SEQ)      // 4096
#define NQKV  (3*DIM)          // 3072

// Scratch (device globals: allocation-free)
__device__ float g_q[BATCH*HEADS*SEQ*HD];     // [b,h,s,d]
__device__ float g_k[BATCH*HEADS*SEQ*HD];
__device__ float g_v[BATCH*HEADS*SEQ*HD];
__device__ float g_attn[BATCH*SEQ*DIM];       // [b,s,h*64+d] (tf32-rounded)
__device__ float g_xr[MROWS*DIM];             // x rounded to tf32
__device__ float g_wqkvr[NQKV*DIM];           // w_qkv rounded to tf32
__device__ float g_wprojr[DIM*DIM];           // w_proj rounded to tf32

// ---------------------------------------------------------------------------
// helpers
// ---------------------------------------------------------------------------
__device__ __forceinline__ uint32_t f2tf32(float f) {
    uint32_t u;
    asm("cvt.rna.tf32.f32 %0, %1;" : "=r"(u) : "f"(f));
    return u;
}
__device__ __forceinline__ float ftf32(float f) { return __uint_as_float(f2tf32(f)); }

__device__ __forceinline__ void mma_tf32(float c[4], const uint32_t a[4], const uint32_t b[2]) {
    asm volatile(
        "mma.sync.aligned.m16n8k8.row.col.f32.tf32.tf32.f32 "
        "{%0,%1,%2,%3},{%4,%5,%6,%7},{%8,%9},{%0,%1,%2,%3};\n"
        : "+f"(c[0]), "+f"(c[1]), "+f"(c[2]), "+f"(c[3])
        : "r"(a[0]), "r"(a[1]), "r"(a[2]), "r"(a[3]), "r"(b[0]), "r"(b[1]));
}

// ---------------------------------------------------------------------------
// Elementwise tf32 rounding pre-pass (RNA). n must be divisible by 4.
// ---------------------------------------------------------------------------
__global__ __launch_bounds__(256)
void round_tf32_kernel(const float* __restrict__ in, float* __restrict__ out, int n4)
{
    int i = blockIdx.x * 256 + threadIdx.x;
    if (i < n4) {
        float4 v = ((const float4*)in)[i];
        ((float4*)out)[i] = make_float4(ftf32(v.x), ftf32(v.y), ftf32(v.z), ftf32(v.w));
    }
}

// ---------------------------------------------------------------------------
// TF32 GEMM: C[m,n] = sum_k A[m,k]*W[n,k] + bias[n]
// A, W must already be tf32-rounded. No cvt in the mainloop.
// BM=BN=128, BK=32, 256 threads, cp.async 2-stage, warp tile 32x64.
// ---------------------------------------------------------------------------
#define PK 36
#define GEMM_SMEM (2*2*128*PK*4)

template<int SCATTER>
__global__ __launch_bounds__(256)
void gemm_tf32(const float* __restrict__ A,
               const float* __restrict__ W,
               const float* __restrict__ bias,
               float* __restrict__ out)
{
    extern __shared__ float sm[];
    float* As = sm;               // [2][128][PK]
    float* Bs = sm + 2*128*PK;    // [2][128][PK]

    const int tid  = threadIdx.x;
    const int wid  = tid >> 5;
    const int lane = tid & 31;
    const int m0 = blockIdx.y * 128;
    const int n0 = blockIdx.x * 128;
    const int wm = (wid & 3) * 32;
    const int wn = (wid >> 2) * 64;
    const int tg = lane >> 2;     // 0..7
    const int tk = lane & 3;      // 0..3

    float acc[2][8][4];
#pragma unroll
    for (int mt = 0; mt < 2; ++mt)
#pragma unroll
        for (int nt = 0; nt < 8; ++nt)
#pragma unroll
            for (int c = 0; c < 4; ++c) acc[mt][nt][c] = 0.f;

    const int K = 1024;
    const int NS = K / 32;

    auto stage = [&](int s, int buf) {
        const int k0 = s * 32;
#pragma unroll
        for (int i = 0; i < 4; ++i) {
            const int t   = tid + i * 256;   // 0..1023
            const int row = t >> 3;          // 0..127
            const int kc  = (t & 7) << 2;    // 0..28
            uint32_t sa = (uint32_t)__cvta_generic_to_shared(
                &As[buf*128*PK + row*PK + kc]);
            const float* ga = &A[(long)(m0 + row) * K + k0 + kc];
            asm volatile("cp.async.cg.shared.global [%0], [%1], 16;\n"
                         :: "r"(sa), "l"(ga));
            uint32_t sb = (uint32_t)__cvta_generic_to_shared(
                &Bs[buf*128*PK + row*PK + kc]);
            const float* gb = &W[(long)(n0 + row) * K + k0 + kc];
            asm volatile("cp.async.cg.shared.global [%0], [%1], 16;\n"
                         :: "r"(sb), "l"(gb));
        }
        asm volatile("cp.async.commit_group;\n");
    };

    stage(0, 0);

    for (int s = 0; s < NS; ++s) {
        const int buf = s & 1;
        if (s + 1 < NS) {
            stage(s + 1, buf ^ 1);
            asm volatile("cp.async.wait_group 1;\n");
        } else {
            asm volatile("cp.async.wait_group 0;\n");
        }
        __syncthreads();

        const float* as = &As[buf*128*PK];
        const float* bs = &Bs[buf*128*PK];
#pragma unroll
        for (int k8 = 0; k8 < 32; k8 += 8) {
            uint32_t af[2][4], bf[8][2];
#pragma unroll
            for (int mt = 0; mt < 2; ++mt) {
                const float* p = &as[(wm + mt*16 + tg)*PK + k8 + tk];
                af[mt][0] = __float_as_uint(p[0]);
                af[mt][1] = __float_as_uint(p[8*PK]);
                af[mt][2] = __float_as_uint(p[4]);
                af[mt][3] = __float_as_uint(p[8*PK + 4]);
            }
#pragma unroll
            for (int nt = 0; nt < 8; ++nt) {
                const float* p = &bs[(wn + nt*8 + tg)*PK + k8 + tk];
                bf[nt][0] = __float_as_uint(p[0]);
                bf[nt][1] = __float_as_uint(p[4]);
            }
#pragma unroll
            for (int mt = 0; mt < 2; ++mt)
#pragma unroll
                for (int nt = 0; nt < 8; ++nt)
                    mma_tf32(acc[mt][nt], af[mt], bf[nt]);
        }
        __syncthreads();
    }

    // epilogue
#pragma unroll
    for (int mt = 0; mt < 2; ++mt) {
#pragma unroll
        for (int nt = 0; nt < 8; ++nt) {
#pragma unroll
            for (int c = 0; c < 4; ++c) {
                const int m = m0 + wm + mt*16 + tg + ((c >= 2) ? 8 : 0);
                const int n = n0 + wn + nt*8 + 2*tk + (c & 1);
                const float v = acc[mt][nt][c] + bias[n];
                if (SCATTER) {
                    const int b = m >> 11, sq = m & 2047;
                    const int part = n >> 10, h = (n >> 6) & 15, d = n & 63;
                    float* dst = (part == 0) ? g_q : (part == 1) ? g_k : g_v;
                    dst[((((long)b*HEADS + h)*SEQ) + sq)*HD + d] = ftf32(v);
                } else {
                    out[(long)m * 1024 + n] = v;
                }
            }
        }
    }
}

// ---------------------------------------------------------------------------
// Flash attention v3 (register-resident FA2 style, TF32 mma).
// BQ=128, BKV=64, 256 threads = 8 warps; each warp owns 16 rows.
// Q fragments in registers (pre-scaled). S/softmax fully in registers.
// P handoff via per-warp smem + syncwarp. cp.async double-buffered K/V.
// ---------------------------------------------------------------------------
#define KP3 68
#define VP3 72
#define PP3 68
#define F3_KOFF 0
#define F3_VOFF (2*64*KP3)
#define F3_POFF (F3_VOFF + 2*64*VP3)
#define F3_SMEM ((F3_POFF + 8*16*PP3)*4)   // 106496 bytes

__global__ __launch_bounds__(256, 2)
void flash3(float* __restrict__ Ob)
{
    extern __shared__ float sm[];
    float* Ksm = sm + F3_KOFF;   // [2][64][KP3]
    float* Vsm = sm + F3_VOFF;   // [2][64][VP3]
    float* Psm = sm + F3_POFF;   // [8 warps][16][PP3]

    const int tid  = threadIdx.x;
    const int wid  = tid >> 5;
    const int lane = tid & 31;
    const int tg = lane >> 2;    // 0..7
    const int tk = lane & 3;     // 0..3
    const int bh = blockIdx.y;
    const int q0 = blockIdx.x * 128;
    const int wm = wid * 16;

    const float* Qg = g_q + ((long)bh*SEQ + q0) * HD;
    const float* Kg = g_k + (long)bh*SEQ*HD;
    const float* Vg = g_v + (long)bh*SEQ*HD;
    float* Pw = Psm + wid*16*PP3;

    // Q fragments in registers, pre-scaled by 1/sqrt(64)=0.125 (exact pow2)
    uint32_t qf[8][4];
#pragma unroll
    for (int i = 0; i < 8; ++i) {
        const int k = i * 8;
        qf[i][0] = __float_as_uint(Qg[(wm+tg)*HD   + k+tk]   * 0.125f);
        qf[i][1] = __float_as_uint(Qg[(wm+tg+8)*HD + k+tk]   * 0.125f);
        qf[i][2] = __float_as_uint(Qg[(wm+tg)*HD   + k+tk+4] * 0.125f);
        qf[i][3] = __float_as_uint(Qg[(wm+tg+8)*HD + k+tk+4] * 0.125f);
    }

    float oacc[8][4];
#pragma unroll
    for (int nt = 0; nt < 8; ++nt)
#pragma unroll
        for (int c = 0; c < 4; ++c) oacc[nt][c] = 0.f;
    float m0 = -1e30f, m1 = -1e30f, l0 = 0.f, l1 = 0.f;

    auto stage = [&](int s, int b2) {
        const float* Kt = Kg + (long)s*64*HD;
        const float* Vt = Vg + (long)s*64*HD;
#pragma unroll
        for (int i = 0; i < 4; ++i) {
            const int t = tid + i*256;       // 0..1023
            const int r = t >> 4;            // 0..63
            const int c = (t & 15) << 2;     // 0..60
            uint32_t dk = (uint32_t)__cvta_generic_to_shared(
                &Ksm[b2*64*KP3 + r*KP3 + c]);
            asm volatile("cp.async.cg.shared.global [%0], [%1], 16;\n"
                         :: "r"(dk), "l"(&Kt[r*HD + c]));
            uint32_t dv = (uint32_t)__cvta_generic_to_shared(
                &Vsm[b2*64*VP3 + r*VP3 + c]);
            asm volatile("cp.async.cg.shared.global [%0], [%1], 16;\n"
                         :: "r"(dv), "l"(&Vt[r*HD + c]));
        }
        asm volatile("cp.async.commit_group;\n");
    };

    stage(0, 0);

    const int NT = SEQ / 64;   // 32
    for (int kt = 0; kt < NT; ++kt) {
        const int buf = kt & 1;
        if (kt + 1 < NT) {
            stage(kt + 1, buf ^ 1);
            asm volatile("cp.async.wait_group 1;\n");
        } else {
            asm volatile("cp.async.wait_group 0;\n");
        }
        __syncthreads();

        const float* Kb = &Ksm[buf*64*KP3];
        const float* Vb = &Vsm[buf*64*VP3];

        // ---- S = (Q*scale) K^T : 16x64 per warp, in registers ----
        float sacc[8][4];
#pragma unroll
        for (int nt = 0; nt < 8; ++nt)
#pragma unroll
            for (int c = 0; c < 4; ++c) sacc[nt][c] = 0.f;
#pragma unroll
        for (int i = 0; i < 8; ++i) {
            const int k8 = i * 8;
            uint32_t bf[8][2];
#pragma unroll
            for (int nt = 0; nt < 8; ++nt) {
                const float* p = &Kb[(nt*8 + tg)*KP3 + k8 + tk];
                bf[nt][0] = __float_as_uint(p[0]);
                bf[nt][1] = __float_as_uint(p[4]);
            }
#pragma unroll
            for (int nt = 0; nt < 8; ++nt)
                mma_tf32(sacc[nt], qf[i], bf[nt]);
        }

        // ---- online softmax, fully in registers ----
        float r0 = -1e30f, r1 = -1e30f;
#pragma unroll
        for (int nt = 0; nt < 8; ++nt) {
            r0 = fmaxf(r0, fmaxf(sacc[nt][0], sacc[nt][1]));
            r1 = fmaxf(r1, fmaxf(sacc[nt][2], sacc[nt][3]));
        }
        r0 = fmaxf(r0, __shfl_xor_sync(0xffffffffu, r0, 1));
        r0 = fmaxf(r0, __shfl_xor_sync(0xffffffffu, r0, 2));
        r1 = fmaxf(r1, __shfl_xor_sync(0xffffffffu, r1, 1));
        r1 = fmaxf(r1, __shfl_xor_sync(0xffffffffu, r1, 2));
        const float mn0 = fmaxf(m0, r0);
        const float mn1 = fmaxf(m1, r1);
        const float a0 = __expf(m0 - mn0);
        const float a1 = __expf(m1 - mn1);
        float s0 = 0.f, s1 = 0.f;
#pragma unroll
        for (int nt = 0; nt < 8; ++nt) {
            float p0 = ftf32(__expf(sacc[nt][0] - mn0));
            float p1 = ftf32(__expf(sacc[nt][1] - mn0));
            float p2 = ftf32(__expf(sacc[nt][2] - mn1));
            float p3 = ftf32(__expf(sacc[nt][3] - mn1));
            sacc[nt][0] = p0; sacc[nt][1] = p1;
            sacc[nt][2] = p2; sacc[nt][3] = p3;
            s0 += p0 + p1;
            s1 += p2 + p3;
        }
        s0 += __shfl_xor_sync(0xffffffffu, s0, 1);
        s0 += __shfl_xor_sync(0xffffffffu, s0, 2);
        s1 += __shfl_xor_sync(0xffffffffu, s1, 1);
        s1 += __shfl_xor_sync(0xffffffffu, s1, 2);
        l0 = l0 * a0 + s0;
        l1 = l1 * a1 + s1;
        m0 = mn0; m1 = mn1;
#pragma unroll
        for (int nt = 0; nt < 8; ++nt) {
            oacc[nt][0] *= a0; oacc[nt][1] *= a0;
            oacc[nt][2] *= a1; oacc[nt][3] *= a1;
        }

        // ---- P to per-warp smem (C-frag -> A-frag layout fix) ----
#pragma unroll
        for (int nt = 0; nt < 8; ++nt) {
            *(float2*)&Pw[tg*PP3     + nt*8 + 2*tk] = make_float2(sacc[nt][0], sacc[nt][1]);
            *(float2*)&Pw[(tg+8)*PP3 + nt*8 + 2*tk] = make_float2(sacc[nt][2], sacc[nt][3]);
        }
        __syncwarp();

        // ---- O += P @ V ----
#pragma unroll
        for (int i = 0; i < 8; ++i) {
            const int k8 = i * 8;
            uint32_t af[4];
            af[0] = __float_as_uint(Pw[tg*PP3     + k8 + tk]);
            af[1] = __float_as_uint(Pw[(tg+8)*PP3 + k8 + tk]);
            af[2] = __float_as_uint(Pw[tg*PP3     + k8 + tk + 4]);
            af[3] = __float_as_uint(Pw[(tg+8)*PP3 + k8 + tk + 4]);
            uint32_t bf[8][2];
#pragma unroll
            for (int nt = 0; nt < 8; ++nt) {
                bf[nt][0] = __float_as_uint(Vb[(k8+tk)*VP3   + nt*8 + tg]);
                bf[nt][1] = __float_as_uint(Vb[(k8+tk+4)*VP3 + nt*8 + tg]);
            }
#pragma unroll
            for (int nt = 0; nt < 8; ++nt)
                mma_tf32(oacc[nt], af, bf[nt]);
        }
        __syncthreads();   // all warps done with buf before it is restaged
    }

    // ---- finalize + store (tf32-rounded) to [B,S,D] ----
    const int b = bh >> 4, h = bh & 15;
    const float i0 = 1.f / l0;
    const float i1 = 1.f / l1;
    const long row0 = (long)b*SEQ + q0 + wm + tg;
    const long row1 = row0 + 8;
#pragma unroll
    for (int nt = 0; nt < 8; ++nt) {
        const int col = h*HD + nt*8 + 2*tk;
        *(float2*)&Ob[row0*DIM + col] =
            make_float2(ftf32(oacc[nt][0]*i0), ftf32(oacc[nt][1]*i0));
        *(float2*)&Ob[row1*DIM + col] =
            make_float2(ftf32(oacc[nt][2]*i1), ftf32(oacc[nt][3]*i1));
    }
}

// ---------------------------------------------------------------------------
extern "C" void kernel_launch(void* const* d_in, const int* in_sizes, int n_in,
                              void* d_out, int out_size)
{
    const float* x      = (const float*)d_in[0];
    const float* w_qkv  = (const float*)d_in[1];
    const float* b_qkv  = (const float*)d_in[2];
    const float* w_proj = (const float*)d_in[3];
    const float* b_proj = (const float*)d_in[4];
    float* out = (float*)d_out;

    float *attn_ptr = nullptr, *xr = nullptr, *wqkvr = nullptr, *wprojr = nullptr;
    cudaGetSymbolAddress((void**)&attn_ptr, g_attn);
    cudaGetSymbolAddress((void**)&xr, g_xr);
    cudaGetSymbolAddress((void**)&wqkvr, g_wqkvr);
    cudaGetSymbolAddress((void**)&wprojr, g_wprojr);

    static bool attr_done = false;
    if (!attr_done) {
        cudaFuncSetAttribute(gemm_tf32<1>,
            cudaFuncAttributeMaxDynamicSharedMemorySize, GEMM_SMEM);
        cudaFuncSetAttribute(gemm_tf32<0>,
            cudaFuncAttributeMaxDynamicSharedMemorySize, GEMM_SMEM);
        cudaFuncSetAttribute(flash3,
            cudaFuncAttributeMaxDynamicSharedMemorySize, F3_SMEM);
        attr_done = true;
    }

    // 0) tf32 rounding pre-pass (RNA) for GEMM operands
    {
        int n4x = MROWS*DIM/4, n4q = NQKV*DIM/4, n4p = DIM*DIM/4;
        round_tf32_kernel<<<(n4x+255)/256, 256>>>(x, xr, n4x);
        round_tf32_kernel<<<(n4q+255)/256, 256>>>(w_qkv, wqkvr, n4q);
        round_tf32_kernel<<<(n4p+255)/256, 256>>>(w_proj, wprojr, n4p);
    }
    // 1) QKV GEMM + bias -> scatter into Q/K/V [b,h,s,d] (tf32-rounded)
    {
        dim3 grid(NQKV/128, MROWS/128);   // (24, 32)
        gemm_tf32<1><<<grid, 256, GEMM_SMEM>>>(xr, wqkvr, b_qkv, nullptr);
    }
    // 2) flash attention v3 -> g_attn [b,s,D] (tf32-rounded)
    {
        dim3 grid(SEQ/128, BATCH*HEADS);  // (16, 32)
        flash3<<<grid, 256, F3_SMEM>>>(attn_ptr);
    }
    // 3) output projection + bias -> d_out
    {
        dim3 grid(DIM/128, MROWS/128);    // (8, 32)
        gemm_tf32<0><<<grid, 256, GEMM_SMEM>>>(attn_ptr, wprojr, b_proj, out);
    }
}